// round 16
// baseline (speedup 1.0000x reference)
#include <cuda_runtime.h>
#include <cuda_bf16.h>
#include <cstdint>

// PCEN: out = (E / (eps + M)^alpha + delta)^r - delta^r
// with causal EMA M_t = (1-s) M_{t-1} + s E_t, per (B,C) row over T.
//
// R11 post-mortem: L1 wavefront model confirmed (63.6->37.6% as predicted)
// but dur regressed -> L1 was not binding. With occ 88%, issue 56%, no unit
// >64%, the limiter is exposed latency in the per-block phase structure
// (block-start LDG ~600cyc all warps wait on, x ~5 waves of short blocks).
//
// This version: persistent blocks (740 = 5x148), each processing ~7 rows
// with a 2-stage cp.async pipeline: row i+1 streams into smem buffer B while
// row i is computed from buffer A. Global side of cp.async is coalesced;
// dst uses the 80B-stride padded layout so pass-1 LDS.128 is conflict-free
// (lane banks 0,20,8,28,16,4,24,12 per phase). Compute shape = R9 best
// (CHUNK=16, 256 threads). Output stored direct from registers (STG.128).
//
// Tail: last iteration (no prefetch) uses wait_group 0 explicitly.
//
// eps fold: x_k = eps + M_k obeys x_k = a*x_{k-1} + (s*e_k + eps*s), seed
// x_{-1} = eps (entered at the serial carry) -> saves one FADD per element.
//
// r == 0.5f exactly here (log_r = inv_sigmoid(0.5) = 0) -> u^r is one
// MUFU.SQRT (uniform runtime check; __powf fallback kept).

#define T_LEN   4000
#define THREADS 256
#define CHUNK   16
#define NCHUNK  (T_LEN / CHUNK)   // 250
#define NVEC4   (T_LEN / 4)       // 1000
#define SLOT_STRIDE 5             // float4 slots per 16-elem chunk
#define NSLOTS  (NCHUNK * SLOT_STRIDE)  // 1250 float4 = 20000 B per buffer
#define NWARP   (THREADS / 32)    // 8
#define NBLOCKS 740               // 5 blocks/SM x 148 SMs, one wave
#define EPS     1e-6f
#define MAX_C   1024

// per-channel: {s, a, -alpha, delta, dr, r, pad, pad}
__device__ float g_param_tab[MAX_C * 8];

__device__ __forceinline__ float sqrt_approx(float x) {
    float y;
    asm("sqrt.approx.f32 %0, %1;" : "=f"(y) : "f"(x));
    return y;
}

__device__ __forceinline__ void cp_async16(unsigned int dst_smem, const void* src) {
    asm volatile("cp.async.cg.shared.global [%0], [%1], 16;"
                 :: "r"(dst_smem), "l"(src) : "memory");
}
__device__ __forceinline__ void cp_async_commit() {
    asm volatile("cp.async.commit_group;" ::: "memory");
}
__device__ __forceinline__ void cp_async_wait1() {
    asm volatile("cp.async.wait_group 1;" ::: "memory");
}
__device__ __forceinline__ void cp_async_wait0() {
    asm volatile("cp.async.wait_group 0;" ::: "memory");
}

__global__ void pcen_prep(const float* __restrict__ log_alpha,
                          const float* __restrict__ log_delta,
                          const float* __restrict__ log_r,
                          const float* __restrict__ log_s,
                          int C)
{
    int c = blockIdx.x * blockDim.x + threadIdx.x;
    if (c < C) {
        float s     = 1.0f / (1.0f + __expf(-log_s[c]));
        float alpha = 1.0f / (1.0f + __expf(-log_alpha[c]));
        float delta = __logf(1.0f + __expf(log_delta[c]));
        float r     = 1.0f / (1.0f + __expf(-log_r[c]));
        float dr    = __powf(delta, r);
        float* p = &g_param_tab[c * 8];
        p[0] = s;
        p[1] = 1.0f - s;
        p[2] = -alpha;
        p[3] = delta;
        p[4] = dr;
        p[5] = r;
    }
}

__global__ __launch_bounds__(THREADS)
void pcen_kernel(const float* __restrict__ E,
                 float* __restrict__ out,
                 int C, int rows)
{
    __shared__ float4 buf[2][NSLOTS];
    __shared__ float warp_sum[NWARP];
    __shared__ float warp_pref[NWARP];

    const int tid  = threadIdx.x;
    const int lane = tid & 31;
    const int wid  = tid >> 5;
    const int stride = gridDim.x;

    const unsigned int sb0 = (unsigned int)__cvta_generic_to_shared(&buf[0][0]);
    const unsigned int sb1 = (unsigned int)__cvta_generic_to_shared(&buf[1][0]);

    // issue coalesced cp.async of one row into buffer base (padded layout)
    auto issue_load = [&](unsigned int sbase, int row) {
        const float4* src = (const float4*)(E + (size_t)row * T_LEN);
        #pragma unroll
        for (int k = 0; k < 4; k++) {
            int j = tid + k * THREADS;
            if (j < NVEC4) {
                unsigned int dst = sbase + (unsigned int)(j + (j >> 2)) * 16u;
                cp_async16(dst, src + j);
            }
        }
    };

    const int row0 = blockIdx.x;
    if (row0 < rows) {
        issue_load(sb0, row0);
    }
    cp_async_commit();

    int cur = 0;
    for (int row = row0; row < rows; row += stride) {
        // prefetch next row into the other buffer
        int next = row + stride;
        if (next < rows) {
            issue_load(cur ? sb0 : sb1, next);
            cp_async_commit();
            cp_async_wait1();    // current row landed; next may stay in flight
        } else {
            cp_async_wait0();    // tail: ensure current row landed
        }
        __syncthreads();

        // --- per-channel params ---
        const int c = row % C;
        const float4 P0 = *(const float4*)&g_param_tab[c * 8];
        const float2 P1 = *(const float2*)&g_param_tab[c * 8 + 4];
        const float s      = P0.x;
        const float a      = P0.y;
        const float nalpha = P0.z;   // -alpha
        const float delta  = P0.w;
        const float dr     = P1.x;
        const float r      = P1.y;
        const float ceps   = EPS * s;

        // --- pass 1: thread-local scan of x-recurrence (LDS.128, no conflicts) ---
        float ev[CHUNK];
        float local = 0.0f;
        const bool active = (tid < NCHUNK);
        const int slot = tid * SLOT_STRIDE;
        if (active) {
            #pragma unroll
            for (int q = 0; q < 4; q++) {
                float4 v = buf[cur][slot + q];
                ev[4*q + 0] = v.x;
                ev[4*q + 1] = v.y;
                ev[4*q + 2] = v.z;
                ev[4*q + 3] = v.w;
            }
            #pragma unroll
            for (int k = 0; k < CHUNK; k++) {
                float t = __fmaf_rn(s, ev[k], ceps);
                local = __fmaf_rn(a, local, t);
            }
        }

        // A = a^16 (chunk ratio)
        float A = a * a;
        A = A * A;
        A = A * A;
        A = A * A;

        // --- warp Hillis-Steele scan; Apow = A^lane built from doubling ---
        float p = local;
        float w = A;
        float Apow = 1.0f;
        #pragma unroll
        for (int d = 1; d < 32; d <<= 1) {
            float up = __shfl_up_sync(0xffffffffu, p, d);
            if (lane >= d) p += w * up;
            if (lane & d)  Apow *= w;
            w = w * w;
        }
        const float A32 = w;     // A^32 = a^512 per-warp ratio

        float pe = __shfl_up_sync(0xffffffffu, p, 1);
        if (lane == 0) pe = 0.0f;

        if (lane == 31) warp_sum[wid] = p;
        __syncthreads();

        // serial carry across 8 warps; seed = EPS (x_{-1})
        if (tid == 0) {
            float acc = EPS;
            #pragma unroll
            for (int j = 0; j < NWARP; j++) {
                warp_pref[j] = acc;
                acc = __fmaf_rn(A32, acc, warp_sum[j]);
            }
        }
        __syncthreads();

        // --- pass 2: recompute x with true incoming state, PCEN math, STG ---
        if (active) {
            float x = __fmaf_rn(Apow, warp_pref[wid], pe);  // x before chunk
            if (r == 0.5f) {
                #pragma unroll
                for (int k = 0; k < CHUNK; k++) {
                    float t = __fmaf_rn(s, ev[k], ceps);
                    x = __fmaf_rn(a, x, t);
                    float pw = __expf(nalpha * __logf(x));   // x^{-alpha}
                    float u  = __fmaf_rn(ev[k], pw, delta);
                    ev[k]    = sqrt_approx(u) - dr;          // u^0.5
                }
            } else {
                #pragma unroll
                for (int k = 0; k < CHUNK; k++) {
                    float t = __fmaf_rn(s, ev[k], ceps);
                    x = __fmaf_rn(a, x, t);
                    float pw = __powf(x, nalpha);
                    float u  = __fmaf_rn(ev[k], pw, delta);
                    ev[k]    = __powf(u, r) - dr;
                }
            }
            float4* dst = (float4*)(out + (size_t)row * T_LEN) + tid * 4;
            float4 o0 = {ev[0],  ev[1],  ev[2],  ev[3]};
            float4 o1 = {ev[4],  ev[5],  ev[6],  ev[7]};
            float4 o2 = {ev[8],  ev[9],  ev[10], ev[11]};
            float4 o3 = {ev[12], ev[13], ev[14], ev[15]};
            dst[0] = o0;
            dst[1] = o1;
            dst[2] = o2;
            dst[3] = o3;
        }
        cur ^= 1;
        // no trailing barrier needed: next iteration's cp.async targets the
        // buffer whose reads all completed before this iteration's carry
        // barriers, which every thread has passed.
    }
}

extern "C" void kernel_launch(void* const* d_in, const int* in_sizes, int n_in,
                              void* d_out, int out_size)
{
    const float* E         = (const float*)d_in[0];
    const float* log_alpha = (const float*)d_in[1];
    const float* log_delta = (const float*)d_in[2];
    const float* log_r     = (const float*)d_in[3];
    const float* log_s     = (const float*)d_in[4];
    float*       out       = (float*)d_out;

    const int C    = in_sizes[1];
    const int rows = in_sizes[0] / T_LEN;   // B*C

    const int grid = rows < NBLOCKS ? rows : NBLOCKS;

    pcen_prep<<<(C + 63) / 64, 64>>>(log_alpha, log_delta, log_r, log_s, C);
    pcen_kernel<<<grid, THREADS>>>(E, out, C, rows);
}